// round 8
// baseline (speedup 1.0000x reference)
#include <cuda_runtime.h>
#include <cuda_fp16.h>
#include <cstdint>
#include <cstddef>

// Problem dims (fixed)
#define B_   16
#define TQ_  2048
#define TK_  2048
#define D_   1024

#define NGRP 4
#define BPG  (B_ / NGRP)    // batches per group = 4

// ---------------------------------------------------------------------------
// Scratch (static __device__ arrays = sanctioned no-alloc scratch)
// fp16 hi/lo split layouts: row-major [rows, 2*K], hi in cols [0,K), lo in [K,2K).
// Alignment fp16 buffer is hi-only: [rows, TK]. encT is hi-only: [B][D, TK].
// ---------------------------------------------------------------------------
__device__ __half g_dec16 [(size_t)B_ * TQ_ * 2 * D_];   // [B*TQ, 2D]
__device__ __half g_enc16 [(size_t)B_ * TK_ * 2 * D_];   // [B*TK, 2D]
__device__ __half g_encT16[(size_t)B_ * D_  * TK_];      // [B][D, TK] hi only
__device__ __half g_keys16[(size_t)B_ * TK_ * 2 * D_];   // [B*TK, 2D]
__device__ __half g_alg16 [(size_t)B_ * TQ_ * TK_];      // [B*TQ, TK] hi only
__device__ __half g_w16T  [(size_t)D_ * 2 * D_];         // [D, 2D]

__device__ __forceinline__ uint32_t smem_u32(const void* p) {
    return (uint32_t)__cvta_generic_to_shared(p);
}

#define SW128(x) ((x) ^ (((x) >> 3) & 0x70))

// ---------------------------------------------------------------------------
// HMMA GEMM, fused hi/lo segments:
//   NSEG=3: C = hiA·hiB^T + loA·hiB^T + hiA·loB^T in ONE K-pass per chunk.
//           Stage holds 4 tiles (hiA,loA,hiB,loB) = 96KB; NS=2 stages.
//   NSEG=1: plain C = A·B^T. Stage holds 2 tiles = 48KB; NS=4 stages.
// A,B fp16 row-major K-major (row strides lda/ldb); hi at col [0,K), lo [K,2K).
// CTA tile 128x256, K-chunk 64, 8 warps (2M x 4N), warp tile 64x64,
// mma.sync.m16n8k16.
// EPI=0: fp32 C.  EPI=1: bias add + hi/lo fp16 out (hi at n, lo at loOff+n).
// ---------------------------------------------------------------------------
#define BM  128
#define BN  256
#define KC  64
static constexpr int GEMM_SMEM = 196608;     // 192KB both configs

__device__ __forceinline__ void cpa16(uint32_t dst, const void* src) {
    asm volatile("cp.async.cg.shared.global [%0], [%1], 16;" :: "r"(dst), "l"(src));
}

__device__ __forceinline__ void ldsm4(uint32_t* r, uint32_t addr) {
    asm volatile("ldmatrix.sync.aligned.m8n8.x4.shared.b16 {%0,%1,%2,%3}, [%4];"
                 : "=r"(r[0]), "=r"(r[1]), "=r"(r[2]), "=r"(r[3]) : "r"(addr));
}

__device__ __forceinline__ void mma16816(float* d, const uint32_t* a,
                                         const uint32_t b0, const uint32_t b1) {
    asm volatile("mma.sync.aligned.m16n8k16.row.col.f32.f16.f16.f32 "
                 "{%0,%1,%2,%3}, {%4,%5,%6,%7}, {%8,%9}, {%0,%1,%2,%3};"
                 : "+f"(d[0]), "+f"(d[1]), "+f"(d[2]), "+f"(d[3])
                 : "r"(a[0]), "r"(a[1]), "r"(a[2]), "r"(a[3]), "r"(b0), "r"(b1));
}

// Stage tile offsets
//  NSEG=3: hiA @0 (16KB) | loA @16K (16KB) | hiB @32K (32KB) | loB @64K (32KB)
//  NSEG=1: A @0 (16KB) | B @16K (32KB)
template<int NSEG>
__device__ __forceinline__ void load_chunk(const __half* A, const __half* Bm,
                                           int lda, int ldb, int m0, int n0,
                                           int K, int kin, uint32_t stage_base,
                                           int tid) {
    const int ka = kin * KC;
    const uint32_t saH = stage_base;
    const uint32_t saL = stage_base + 16384;
    const uint32_t sbH = stage_base + (NSEG == 3 ? 32768 : 16384);
    const uint32_t sbL = stage_base + 65536;
#pragma unroll
    for (int it = 0; it < (BM * 8) / 256; ++it) {        // A: 128 rows x 8 segs
        int idx = tid + it * 256;
        int row = idx >> 3, c16 = idx & 7;
        const __half* g = A + (size_t)(m0 + row) * lda + ka + c16 * 8;
        uint32_t sw = SW128(row * 128 + c16 * 16);
        cpa16(saH + sw, g);
        if (NSEG == 3) cpa16(saL + sw, g + K);
    }
#pragma unroll
    for (int it = 0; it < (BN * 8) / 256; ++it) {        // B: 256 rows x 8 segs
        int idx = tid + it * 256;
        int row = idx >> 3, c16 = idx & 7;
        const __half* g = Bm + (size_t)(n0 + row) * ldb + ka + c16 * 8;
        uint32_t sw = SW128(row * 128 + c16 * 16);
        cpa16(sbH + sw, g);
        if (NSEG == 3) cpa16(sbL + sw, g + K);
    }
}

template<int EPI, int NSEG>
__global__ __launch_bounds__(256, 1)
void gemm_hmma(const __half* __restrict__ A, const __half* __restrict__ Bm,
               const float* __restrict__ bias,
               float* __restrict__ Cf, __half* __restrict__ Ch,
               int lda, int ldb, int ldc, int K, int loOff,
               size_t sA, size_t sB, size_t sC)
{
    constexpr int NSs = (NSEG == 3) ? 2 : 4;
    constexpr int STG = (NSEG == 3) ? 98304 : 49152;

    extern __shared__ __align__(1024) char smem[];
    const uint32_t smem_base = smem_u32(smem);
    const int tid = threadIdx.x, wid = tid >> 5, lid = tid & 31;
    const int bz = blockIdx.z;
    A  += (size_t)bz * sA;
    Bm += (size_t)bz * sB;

    const int m0 = blockIdx.y * BM;
    const int n0 = blockIdx.x * BN;

    const int nk = K / KC;

    // warp layout: 2 (M) x 4 (N); warp tile 64x64
    const int warp_m = wid & 1;
    const int warp_n = wid >> 1;

    float acc[4][8][4];
#pragma unroll
    for (int t = 0; t < 4; ++t)
#pragma unroll
        for (int j = 0; j < 8; ++j)
#pragma unroll
            for (int c = 0; c < 4; ++c) acc[t][j][c] = 0.f;

    // ldmatrix per-lane address components
    const int aRow = warp_m * 64 + (lid & 15);
    const int aK   = (lid & 16) >> 1;       // 0 or 8
    const int bRow = warp_n * 64 + (lid & 7) + ((lid & 16) >> 1);
    const int bK   = (lid & 8);             // 0 or 8

    // ---- prologue: fill NSs-1 stages ----
#pragma unroll
    for (int i = 0; i < NSs - 1; ++i) {
        load_chunk<NSEG>(A, Bm, lda, ldb, m0, n0, K, i,
                         smem_base + i * STG, tid);
        asm volatile("cp.async.commit_group;" ::: "memory");
    }

    for (int cc = 0; cc < nk; ++cc) {
        asm volatile("cp.async.wait_group %0;" :: "n"(NSs - 2));
        __syncthreads();

        // prefetch chunk cc+NSs-1 into the stage freed at iter cc-1
        {
            const int cl = cc + NSs - 1;
            if (cl < nk)
                load_chunk<NSEG>(A, Bm, lda, ldb, m0, n0, K, cl,
                                 smem_base + (cl & (NSs - 1)) * STG, tid);
            asm volatile("cp.async.commit_group;" ::: "memory");
        }

        // ---- compute on stage cc%NSs ----
        const uint32_t st  = smem_base + (cc & (NSs - 1)) * STG;
        const uint32_t saH = st;
        const uint32_t saL = st + 16384;
        const uint32_t sbH = st + (NSEG == 3 ? 32768 : 16384);
        const uint32_t sbL = st + 65536;
#pragma unroll
        for (int kk = 0; kk < KC; kk += 16) {
            uint32_t aH[4][4], bH[4][4];
#pragma unroll
            for (int t = 0; t < 4; ++t)
                ldsm4(aH[t], saH + SW128((aRow + t * 16) * 128 + (kk + aK) * 2));
#pragma unroll
            for (int g = 0; g < 4; ++g)
                ldsm4(bH[g], sbH + SW128((bRow + g * 16) * 128 + (kk + bK) * 2));
            // P0: hiA x hiB
#pragma unroll
            for (int t = 0; t < 4; ++t)
#pragma unroll
                for (int j = 0; j < 8; ++j)
                    mma16816(acc[t][j], aH[t],
                             bH[j >> 1][(j & 1) * 2], bH[j >> 1][(j & 1) * 2 + 1]);
            if (NSEG == 3) {
                // P1: loA x hiB
                uint32_t aL[4][4];
#pragma unroll
                for (int t = 0; t < 4; ++t)
                    ldsm4(aL[t], saL + SW128((aRow + t * 16) * 128 + (kk + aK) * 2));
#pragma unroll
                for (int t = 0; t < 4; ++t)
#pragma unroll
                    for (int j = 0; j < 8; ++j)
                        mma16816(acc[t][j], aL[t],
                                 bH[j >> 1][(j & 1) * 2], bH[j >> 1][(j & 1) * 2 + 1]);
                // P2: hiA x loB
                uint32_t bL[4][4];
#pragma unroll
                for (int g = 0; g < 4; ++g)
                    ldsm4(bL[g], sbL + SW128((bRow + g * 16) * 128 + (kk + bK) * 2));
#pragma unroll
                for (int t = 0; t < 4; ++t)
#pragma unroll
                    for (int j = 0; j < 8; ++j)
                        mma16816(acc[t][j], aH[t],
                                 bL[j >> 1][(j & 1) * 2], bL[j >> 1][(j & 1) * 2 + 1]);
            }
        }
    }

    // ---- epilogue ----
    const int g8 = lid >> 2;
    const int tg = lid & 3;
#pragma unroll
    for (int t = 0; t < 4; ++t) {
        const int rbase = m0 + warp_m * 64 + t * 16 + g8;
#pragma unroll
        for (int j = 0; j < 8; ++j) {
            const int col = n0 + warp_n * 64 + j * 8 + tg * 2;
            if (EPI == 0) {
                float* p0 = Cf + (size_t)bz * sC + (size_t)rbase * ldc + col;
                float* p1 = p0 + (size_t)8 * ldc;
                ((float2*)p0)[0] = make_float2(acc[t][j][0], acc[t][j][1]);
                ((float2*)p1)[0] = make_float2(acc[t][j][2], acc[t][j][3]);
            } else {
                const float b0 = bias[col], b1 = bias[col + 1];
#pragma unroll
                for (int hrow = 0; hrow < 2; ++hrow) {
                    const int row = rbase + hrow * 8;
                    float v0 = acc[t][j][hrow * 2 + 0] + b0;
                    float v1 = acc[t][j][hrow * 2 + 1] + b1;
                    __half h0 = __float2half_rn(v0), h1 = __float2half_rn(v1);
                    __half l0 = __float2half_rn(v0 - __half2float(h0));
                    __half l1 = __float2half_rn(v1 - __half2float(h1));
                    *(__half2*)(Ch + (size_t)row * ldc + col)         = __halves2half2(h0, h1);
                    *(__half2*)(Ch + (size_t)row * ldc + loOff + col) = __halves2half2(l0, l1);
                }
            }
        }
    }
}

// ---------------------------------------------------------------------------
// fp32 [rows, C] -> fp16 [rows, 2C] hi|lo split
// ---------------------------------------------------------------------------
__global__ void split_rows(const float* __restrict__ in, __half* __restrict__ out,
                           int C, size_t total4)
{
    size_t i = (size_t)blockIdx.x * blockDim.x + threadIdx.x;
    if (i >= total4) return;
    const int c4 = C / 4;
    size_t r = i / c4;
    int c = (int)(i % c4) * 4;
    float4 v = ((const float4*)in)[i];
    __half h0 = __float2half_rn(v.x), h1 = __float2half_rn(v.y);
    __half h2 = __float2half_rn(v.z), h3 = __float2half_rn(v.w);
    __half l0 = __float2half_rn(v.x - __half2float(h0));
    __half l1 = __float2half_rn(v.y - __half2float(h1));
    __half l2 = __float2half_rn(v.z - __half2float(h2));
    __half l3 = __float2half_rn(v.w - __half2float(h3));
    __half* ph = out + r * (size_t)(2 * C) + c;
    ((__half2*)ph)[0] = __halves2half2(h0, h1);
    ((__half2*)ph)[1] = __halves2half2(h2, h3);
    __half* pl = ph + C;
    ((__half2*)pl)[0] = __halves2half2(l0, l1);
    ((__half2*)pl)[1] = __halves2half2(l2, l3);
}

// ---------------------------------------------------------------------------
// fp32 [R, C] -> transposed fp16 [C, R] hi only. Batched via z.
// ---------------------------------------------------------------------------
__global__ void transpose_hi(const float* __restrict__ in, __half* __restrict__ out,
                             int R, int C, size_t sIn, size_t sOut)
{
    __shared__ float t[32][33];
    in  += (size_t)blockIdx.z * sIn;
    out += (size_t)blockIdx.z * sOut;
    const int r0 = blockIdx.x * 32, c0 = blockIdx.y * 32;
    const int tx = threadIdx.x, ty = threadIdx.y;  // 32 x 8
#pragma unroll
    for (int i = 0; i < 4; ++i)
        t[ty + i * 8][tx] = in[(size_t)(r0 + ty + i * 8) * C + c0 + tx];
    __syncthreads();
#pragma unroll
    for (int i = 0; i < 4; ++i) {
        const int cc = c0 + ty + i * 8;
        out[(size_t)cc * R + r0 + tx] = __float2half_rn(t[tx][ty + i * 8]);
    }
}

// ---------------------------------------------------------------------------
// W transpose + hi/lo split: in [D, D] fp32 -> out [D, 2D] fp16,
// out[e][d] = hi(W[d][e]), out[e][D+d] = lo(W[d][e]).
// ---------------------------------------------------------------------------
__global__ void transpose_split_w(const float* __restrict__ in, __half* __restrict__ out)
{
    __shared__ float t[32][33];
    const int r0 = blockIdx.x * 32, c0 = blockIdx.y * 32;
    const int tx = threadIdx.x, ty = threadIdx.y;  // 32 x 8
#pragma unroll
    for (int i = 0; i < 4; ++i)
        t[ty + i * 8][tx] = in[(size_t)(r0 + ty + i * 8) * D_ + c0 + tx];
    __syncthreads();
#pragma unroll
    for (int i = 0; i < 4; ++i) {
        const int cc = c0 + ty + i * 8;
        float v = t[tx][ty + i * 8];
        __half h = __float2half_rn(v);
        __half l = __float2half_rn(v - __half2float(h));
        out[(size_t)cc * (2 * D_) + r0 + tx]      = h;
        out[(size_t)cc * (2 * D_) + D_ + r0 + tx] = l;
    }
}

// ---------------------------------------------------------------------------
// Row softmax over TK_=2048, in place + fp16 (hi-only) emit
// ---------------------------------------------------------------------------
__global__ void softmax2048(float* __restrict__ data, __half* __restrict__ a16)
{
    __shared__ float red[8];
    const size_t row = blockIdx.x;
    float* p = data + row * (size_t)TK_;
    const int tid = threadIdx.x, lane = tid & 31, wid = tid >> 5;

    float4 v0 = ((const float4*)p)[tid];
    float4 v1 = ((const float4*)p)[tid + 256];

    float mx = fmaxf(fmaxf(fmaxf(v0.x, v0.y), fmaxf(v0.z, v0.w)),
                     fmaxf(fmaxf(v1.x, v1.y), fmaxf(v1.z, v1.w)));
#pragma unroll
    for (int o = 16; o > 0; o >>= 1) mx = fmaxf(mx, __shfl_xor_sync(~0u, mx, o));
    if (lane == 0) red[wid] = mx;
    __syncthreads();
    mx = red[0];
#pragma unroll
    for (int w = 1; w < 8; w++) mx = fmaxf(mx, red[w]);
    __syncthreads();

    v0.x = __expf(v0.x - mx); v0.y = __expf(v0.y - mx);
    v0.z = __expf(v0.z - mx); v0.w = __expf(v0.w - mx);
    v1.x = __expf(v1.x - mx); v1.y = __expf(v1.y - mx);
    v1.z = __expf(v1.z - mx); v1.w = __expf(v1.w - mx);

    float s = v0.x + v0.y + v0.z + v0.w + v1.x + v1.y + v1.z + v1.w;
#pragma unroll
    for (int o = 16; o > 0; o >>= 1) s += __shfl_xor_sync(~0u, s, o);
    if (lane == 0) red[wid] = s;
    __syncthreads();
    s = red[0] + red[1] + red[2] + red[3] + red[4] + red[5] + red[6] + red[7];

    const float inv = 1.0f / s;
    v0.x *= inv; v0.y *= inv; v0.z *= inv; v0.w *= inv;
    v1.x *= inv; v1.y *= inv; v1.z *= inv; v1.w *= inv;

    ((float4*)p)[tid]       = v0;
    ((float4*)p)[tid + 256] = v1;

    __half* ah = a16 + row * (size_t)TK_;
    auto emit = [&](int idx, float4 v) {
        ((__half2*)(ah + idx))[0] = __halves2half2(__float2half_rn(v.x), __float2half_rn(v.y));
        ((__half2*)(ah + idx))[1] = __halves2half2(__float2half_rn(v.z), __float2half_rn(v.w));
    };
    emit(tid * 4, v0);
    emit((tid + 256) * 4, v1);
}

// ---------------------------------------------------------------------------
// kernel_launch — two-stream pipelined schedule.
// Main stream (0): enc split, W split, keys GEMM, score(g), context(g).
// Side stream   : dec split, encT transpose, softmax(g).
// Fork/join via events (graph-capturable pattern).
// ---------------------------------------------------------------------------
extern "C" void kernel_launch(void* const* d_in, const int* in_sizes, int n_in,
                              void* d_out, int out_size)
{
    (void)in_sizes; (void)n_in; (void)out_size;

    const float* dec = (const float*)d_in[0];
    const float* enc = (const float*)d_in[1];
    const float* wk  = (const float*)d_in[2];
    const float* wb  = (const float*)d_in[3];

    float* ctx = (float*)d_out;                            // [B, TQ, D]
    float* ali = (float*)d_out + (size_t)B_ * TQ_ * D_;    // [B, TQ, TK]

    __half *dec16, *enc16, *encT16, *keys16, *alg16, *w16T;
    cudaGetSymbolAddress((void**)&dec16,  g_dec16);
    cudaGetSymbolAddress((void**)&enc16,  g_enc16);
    cudaGetSymbolAddress((void**)&encT16, g_encT16);
    cudaGetSymbolAddress((void**)&keys16, g_keys16);
    cudaGetSymbolAddress((void**)&alg16,  g_alg16);
    cudaGetSymbolAddress((void**)&w16T,   g_w16T);

    // Lazily-created side stream + events (host/driver objects; no device alloc).
    static bool s_init = false;
    static cudaStream_t sS;
    static cudaEvent_t evFork, evConv, evScore[NGRP], evSm[NGRP];
    if (!s_init) {
        s_init = true;
        cudaStreamCreateWithFlags(&sS, cudaStreamNonBlocking);
        cudaEventCreateWithFlags(&evFork, cudaEventDisableTiming);
        cudaEventCreateWithFlags(&evConv, cudaEventDisableTiming);
        for (int g = 0; g < NGRP; ++g) {
            cudaEventCreateWithFlags(&evScore[g], cudaEventDisableTiming);
            cudaEventCreateWithFlags(&evSm[g],    cudaEventDisableTiming);
        }
        cudaFuncSetAttribute(gemm_hmma<0,3>, cudaFuncAttributeMaxDynamicSharedMemorySize, GEMM_SMEM);
        cudaFuncSetAttribute(gemm_hmma<1,3>, cudaFuncAttributeMaxDynamicSharedMemorySize, GEMM_SMEM);
        cudaFuncSetAttribute(gemm_hmma<0,1>, cudaFuncAttributeMaxDynamicSharedMemorySize, GEMM_SMEM);
    }

    const size_t t4 = (size_t)B_ * TQ_ * D_ / 4;

    // ---- fork side stream ----
    cudaEventRecord(evFork, 0);
    cudaStreamWaitEvent(sS, evFork, 0);

    // side: dec split + encT transpose (independent of main chain)
    split_rows<<<(unsigned)((t4 + 255) / 256), 256, 0, sS>>>(dec, dec16, D_, t4);
    transpose_hi<<<dim3(TK_ / 32, D_ / 32, B_), dim3(32, 8), 0, sS>>>(
        enc, encT16, TK_, D_, (size_t)TK_ * D_, (size_t)D_ * TK_);
    cudaEventRecord(evConv, sS);

    // main: enc split + W split + keys GEMM
    split_rows<<<(unsigned)((t4 + 255) / 256), 256>>>(enc, enc16, D_, t4);
    transpose_split_w<<<dim3(D_ / 32, D_ / 32), dim3(32, 8)>>>(wk, w16T);
    gemm_hmma<1,3><<<dim3(D_ / BN, (B_ * TK_) / BM, 1), 256, GEMM_SMEM>>>(
        enc16, w16T, wb, nullptr, keys16,
        2 * D_, 2 * D_, 2 * D_, D_, D_, 0, 0, 0);

    // main needs dec16 (and later encT16) from side stream
    cudaStreamWaitEvent(0, evConv, 0);

    // ---- pipelined score -> softmax -> context over batch groups ----
    for (int g = 0; g < NGRP; ++g) {
        const size_t ob = (size_t)g * BPG;
        gemm_hmma<0,3><<<dim3(TK_ / BN, TQ_ / BM, BPG), 256, GEMM_SMEM>>>(
            dec16  + ob * TQ_ * 2 * D_,
            keys16 + ob * TK_ * 2 * D_,
            nullptr,
            ali + ob * TQ_ * TK_, nullptr,
            2 * D_, 2 * D_, TK_, D_, 0,
            (size_t)TQ_ * 2 * D_, (size_t)TK_ * 2 * D_, (size_t)TQ_ * TK_);
        cudaEventRecord(evScore[g], 0);

        cudaStreamWaitEvent(sS, evScore[g], 0);
        softmax2048<<<BPG * TQ_, 256, 0, sS>>>(
            ali + ob * TQ_ * TK_, alg16 + ob * TQ_ * TK_);
        cudaEventRecord(evSm[g], sS);
    }

    for (int g = 0; g < NGRP; ++g) {
        const size_t ob = (size_t)g * BPG;
        cudaStreamWaitEvent(0, evSm[g], 0);
        gemm_hmma<0,1><<<dim3(D_ / BN, TQ_ / BM, BPG), 256, GEMM_SMEM>>>(
            alg16  + ob * TQ_ * TK_,
            encT16 + ob * D_ * TK_,
            nullptr,
            ctx + ob * TQ_ * D_, nullptr,
            TK_, TK_, D_, TK_, 0,
            (size_t)TQ_ * TK_, (size_t)D_ * TK_, (size_t)TQ_ * D_);
    }
}

// round 9
// speedup vs baseline: 1.0643x; 1.0643x over previous
#include <cuda_runtime.h>
#include <cuda_fp16.h>
#include <cstdint>
#include <cstddef>

// Problem dims (fixed)
#define B_   16
#define TQ_  2048
#define TK_  2048
#define D_   1024

#define NGRP 2
#define BPG  (B_ / NGRP)    // batches per group = 8

// ---------------------------------------------------------------------------
// Scratch (static __device__ arrays = sanctioned no-alloc scratch)
// fp16 hi/lo split layouts: row-major [rows, 2*K], hi in cols [0,K), lo in [K,2K).
// Alignment fp16 buffer is hi-only: [rows, TK]. encT is hi-only: [B][D, TK].
// ---------------------------------------------------------------------------
__device__ __half g_dec16 [(size_t)B_ * TQ_ * 2 * D_];   // [B*TQ, 2D]
__device__ __half g_enc16 [(size_t)B_ * TK_ * 2 * D_];   // [B*TK, 2D]
__device__ __half g_encT16[(size_t)B_ * D_  * TK_];      // [B][D, TK] hi only
__device__ __half g_keys16[(size_t)B_ * TK_ * 2 * D_];   // [B*TK, 2D]
__device__ __half g_alg16 [(size_t)B_ * TQ_ * TK_];      // [B*TQ, TK] hi only
__device__ __half g_w16T  [(size_t)D_ * 2 * D_];         // [D, 2D]

__device__ __forceinline__ uint32_t smem_u32(const void* p) {
    return (uint32_t)__cvta_generic_to_shared(p);
}

#define SW128(x) ((x) ^ (((x) >> 3) & 0x70))

// ---------------------------------------------------------------------------
// HMMA GEMM, fused hi/lo segments:
//   NSEG=3: C = hiA·hiB^T + loA·hiB^T + hiA·loB^T in ONE K-pass per chunk.
//           Stage holds 4 tiles (hiA,loA,hiB,loB) = 96KB; NS=2 stages.
//   NSEG=1: plain C = A·B^T. Stage holds 2 tiles = 48KB; NS=4 stages.
// A,B fp16 row-major K-major (row strides lda/ldb); hi at col [0,K), lo [K,2K).
// CTA tile 128x256, K-chunk 64, 8 warps (2M x 4N), warp tile 64x64,
// mma.sync.m16n8k16.
// EPI=0: fp32 C.  EPI=1: bias add + hi/lo fp16 out (hi at n, lo at loOff+n).
// ---------------------------------------------------------------------------
#define BM  128
#define BN  256
#define KC  64
static constexpr int GEMM_SMEM = 196608;     // 192KB both configs

__device__ __forceinline__ void cpa16(uint32_t dst, const void* src) {
    asm volatile("cp.async.cg.shared.global [%0], [%1], 16;" :: "r"(dst), "l"(src));
}

__device__ __forceinline__ void ldsm4(uint32_t* r, uint32_t addr) {
    asm volatile("ldmatrix.sync.aligned.m8n8.x4.shared.b16 {%0,%1,%2,%3}, [%4];"
                 : "=r"(r[0]), "=r"(r[1]), "=r"(r[2]), "=r"(r[3]) : "r"(addr));
}

__device__ __forceinline__ void mma16816(float* d, const uint32_t* a,
                                         const uint32_t b0, const uint32_t b1) {
    asm volatile("mma.sync.aligned.m16n8k16.row.col.f32.f16.f16.f32 "
                 "{%0,%1,%2,%3}, {%4,%5,%6,%7}, {%8,%9}, {%0,%1,%2,%3};"
                 : "+f"(d[0]), "+f"(d[1]), "+f"(d[2]), "+f"(d[3])
                 : "r"(a[0]), "r"(a[1]), "r"(a[2]), "r"(a[3]), "r"(b0), "r"(b1));
}

// Stage tile offsets
//  NSEG=3: hiA @0 (16KB) | loA @16K (16KB) | hiB @32K (32KB) | loB @64K (32KB)
//  NSEG=1: A @0 (16KB) | B @16K (32KB)
template<int NSEG>
__device__ __forceinline__ void load_chunk(const __half* A, const __half* Bm,
                                           int lda, int ldb, int m0, int n0,
                                           int K, int kin, uint32_t stage_base,
                                           int tid) {
    const int ka = kin * KC;
    const uint32_t saH = stage_base;
    const uint32_t saL = stage_base + 16384;
    const uint32_t sbH = stage_base + (NSEG == 3 ? 32768 : 16384);
    const uint32_t sbL = stage_base + 65536;
#pragma unroll
    for (int it = 0; it < (BM * 8) / 256; ++it) {        // A: 128 rows x 8 segs
        int idx = tid + it * 256;
        int row = idx >> 3, c16 = idx & 7;
        const __half* g = A + (size_t)(m0 + row) * lda + ka + c16 * 8;
        uint32_t sw = SW128(row * 128 + c16 * 16);
        cpa16(saH + sw, g);
        if (NSEG == 3) cpa16(saL + sw, g + K);
    }
#pragma unroll
    for (int it = 0; it < (BN * 8) / 256; ++it) {        // B: 256 rows x 8 segs
        int idx = tid + it * 256;
        int row = idx >> 3, c16 = idx & 7;
        const __half* g = Bm + (size_t)(n0 + row) * ldb + ka + c16 * 8;
        uint32_t sw = SW128(row * 128 + c16 * 16);
        cpa16(sbH + sw, g);
        if (NSEG == 3) cpa16(sbL + sw, g + K);
    }
}

template<int EPI, int NSEG>
__global__ __launch_bounds__(256, 1)
void gemm_hmma(const __half* __restrict__ A, const __half* __restrict__ Bm,
               const float* __restrict__ bias,
               float* __restrict__ Cf, __half* __restrict__ Ch,
               int lda, int ldb, int ldc, int K, int loOff,
               size_t sA, size_t sB, size_t sC)
{
    constexpr int NSs = (NSEG == 3) ? 2 : 4;
    constexpr int STG = (NSEG == 3) ? 98304 : 49152;

    extern __shared__ __align__(1024) char smem[];
    const uint32_t smem_base = smem_u32(smem);
    const int tid = threadIdx.x, wid = tid >> 5, lid = tid & 31;
    const int bz = blockIdx.z;
    A  += (size_t)bz * sA;
    Bm += (size_t)bz * sB;

    const int m0 = blockIdx.y * BM;
    const int n0 = blockIdx.x * BN;

    const int nk = K / KC;

    // warp layout: 2 (M) x 4 (N); warp tile 64x64
    const int warp_m = wid & 1;
    const int warp_n = wid >> 1;

    float acc[4][8][4];
#pragma unroll
    for (int t = 0; t < 4; ++t)
#pragma unroll
        for (int j = 0; j < 8; ++j)
#pragma unroll
            for (int c = 0; c < 4; ++c) acc[t][j][c] = 0.f;

    // ldmatrix per-lane address components
    const int aRow = warp_m * 64 + (lid & 15);
    const int aK   = (lid & 16) >> 1;       // 0 or 8
    const int bRow = warp_n * 64 + (lid & 7) + ((lid & 16) >> 1);
    const int bK   = (lid & 8);             // 0 or 8

    // ---- prologue: fill NSs-1 stages ----
#pragma unroll
    for (int i = 0; i < NSs - 1; ++i) {
        load_chunk<NSEG>(A, Bm, lda, ldb, m0, n0, K, i,
                         smem_base + i * STG, tid);
        asm volatile("cp.async.commit_group;" ::: "memory");
    }

    for (int cc = 0; cc < nk; ++cc) {
        asm volatile("cp.async.wait_group %0;" :: "n"(NSs - 2));
        __syncthreads();

        // prefetch chunk cc+NSs-1 into the stage freed at iter cc-1
        {
            const int cl = cc + NSs - 1;
            if (cl < nk)
                load_chunk<NSEG>(A, Bm, lda, ldb, m0, n0, K, cl,
                                 smem_base + (cl & (NSs - 1)) * STG, tid);
            asm volatile("cp.async.commit_group;" ::: "memory");
        }

        // ---- compute on stage cc%NSs ----
        const uint32_t st  = smem_base + (cc & (NSs - 1)) * STG;
        const uint32_t saH = st;
        const uint32_t saL = st + 16384;
        const uint32_t sbH = st + (NSEG == 3 ? 32768 : 16384);
        const uint32_t sbL = st + 65536;
#pragma unroll
        for (int kk = 0; kk < KC; kk += 16) {
            uint32_t aH[4][4], bH[4][4];
#pragma unroll
            for (int t = 0; t < 4; ++t)
                ldsm4(aH[t], saH + SW128((aRow + t * 16) * 128 + (kk + aK) * 2));
#pragma unroll
            for (int g = 0; g < 4; ++g)
                ldsm4(bH[g], sbH + SW128((bRow + g * 16) * 128 + (kk + bK) * 2));
            // P0: hiA x hiB
#pragma unroll
            for (int t = 0; t < 4; ++t)
#pragma unroll
                for (int j = 0; j < 8; ++j)
                    mma16816(acc[t][j], aH[t],
                             bH[j >> 1][(j & 1) * 2], bH[j >> 1][(j & 1) * 2 + 1]);
            if (NSEG == 3) {
                // P1: loA x hiB
                uint32_t aL[4][4];
#pragma unroll
                for (int t = 0; t < 4; ++t)
                    ldsm4(aL[t], saL + SW128((aRow + t * 16) * 128 + (kk + aK) * 2));
#pragma unroll
                for (int t = 0; t < 4; ++t)
#pragma unroll
                    for (int j = 0; j < 8; ++j)
                        mma16816(acc[t][j], aL[t],
                                 bH[j >> 1][(j & 1) * 2], bH[j >> 1][(j & 1) * 2 + 1]);
                // P2: hiA x loB
                uint32_t bL[4][4];
#pragma unroll
                for (int g = 0; g < 4; ++g)
                    ldsm4(bL[g], sbL + SW128((bRow + g * 16) * 128 + (kk + bK) * 2));
#pragma unroll
                for (int t = 0; t < 4; ++t)
#pragma unroll
                    for (int j = 0; j < 8; ++j)
                        mma16816(acc[t][j], aH[t],
                                 bL[j >> 1][(j & 1) * 2], bL[j >> 1][(j & 1) * 2 + 1]);
            }
        }
    }

    // ---- epilogue ----
    const int g8 = lid >> 2;
    const int tg = lid & 3;
#pragma unroll
    for (int t = 0; t < 4; ++t) {
        const int rbase = m0 + warp_m * 64 + t * 16 + g8;
#pragma unroll
        for (int j = 0; j < 8; ++j) {
            const int col = n0 + warp_n * 64 + j * 8 + tg * 2;
            if (EPI == 0) {
                float* p0 = Cf + (size_t)bz * sC + (size_t)rbase * ldc + col;
                float* p1 = p0 + (size_t)8 * ldc;
                ((float2*)p0)[0] = make_float2(acc[t][j][0], acc[t][j][1]);
                ((float2*)p1)[0] = make_float2(acc[t][j][2], acc[t][j][3]);
            } else {
                const float b0 = bias[col], b1 = bias[col + 1];
#pragma unroll
                for (int hrow = 0; hrow < 2; ++hrow) {
                    const int row = rbase + hrow * 8;
                    float v0 = acc[t][j][hrow * 2 + 0] + b0;
                    float v1 = acc[t][j][hrow * 2 + 1] + b1;
                    __half h0 = __float2half_rn(v0), h1 = __float2half_rn(v1);
                    __half l0 = __float2half_rn(v0 - __half2float(h0));
                    __half l1 = __float2half_rn(v1 - __half2float(h1));
                    *(__half2*)(Ch + (size_t)row * ldc + col)         = __halves2half2(h0, h1);
                    *(__half2*)(Ch + (size_t)row * ldc + loOff + col) = __halves2half2(l0, l1);
                }
            }
        }
    }
}

// ---------------------------------------------------------------------------
// fp32 [rows, C] -> fp16 [rows, 2C] hi|lo split
// ---------------------------------------------------------------------------
__global__ void split_rows(const float* __restrict__ in, __half* __restrict__ out,
                           int C, size_t total4)
{
    size_t i = (size_t)blockIdx.x * blockDim.x + threadIdx.x;
    if (i >= total4) return;
    const int c4 = C / 4;
    size_t r = i / c4;
    int c = (int)(i % c4) * 4;
    float4 v = ((const float4*)in)[i];
    __half h0 = __float2half_rn(v.x), h1 = __float2half_rn(v.y);
    __half h2 = __float2half_rn(v.z), h3 = __float2half_rn(v.w);
    __half l0 = __float2half_rn(v.x - __half2float(h0));
    __half l1 = __float2half_rn(v.y - __half2float(h1));
    __half l2 = __float2half_rn(v.z - __half2float(h2));
    __half l3 = __float2half_rn(v.w - __half2float(h3));
    __half* ph = out + r * (size_t)(2 * C) + c;
    ((__half2*)ph)[0] = __halves2half2(h0, h1);
    ((__half2*)ph)[1] = __halves2half2(h2, h3);
    __half* pl = ph + C;
    ((__half2*)pl)[0] = __halves2half2(l0, l1);
    ((__half2*)pl)[1] = __halves2half2(l2, l3);
}

// ---------------------------------------------------------------------------
// fp32 [R, C] -> transposed fp16 [C, R] hi only. Batched via z.
// ---------------------------------------------------------------------------
__global__ void transpose_hi(const float* __restrict__ in, __half* __restrict__ out,
                             int R, int C, size_t sIn, size_t sOut)
{
    __shared__ float t[32][33];
    in  += (size_t)blockIdx.z * sIn;
    out += (size_t)blockIdx.z * sOut;
    const int r0 = blockIdx.x * 32, c0 = blockIdx.y * 32;
    const int tx = threadIdx.x, ty = threadIdx.y;  // 32 x 8
#pragma unroll
    for (int i = 0; i < 4; ++i)
        t[ty + i * 8][tx] = in[(size_t)(r0 + ty + i * 8) * C + c0 + tx];
    __syncthreads();
#pragma unroll
    for (int i = 0; i < 4; ++i) {
        const int cc = c0 + ty + i * 8;
        out[(size_t)cc * R + r0 + tx] = __float2half_rn(t[tx][ty + i * 8]);
    }
}

// ---------------------------------------------------------------------------
// W transpose + hi/lo split: in [D, D] fp32 -> out [D, 2D] fp16,
// out[e][d] = hi(W[d][e]), out[e][D+d] = lo(W[d][e]).
// ---------------------------------------------------------------------------
__global__ void transpose_split_w(const float* __restrict__ in, __half* __restrict__ out)
{
    __shared__ float t[32][33];
    const int r0 = blockIdx.x * 32, c0 = blockIdx.y * 32;
    const int tx = threadIdx.x, ty = threadIdx.y;  // 32 x 8
#pragma unroll
    for (int i = 0; i < 4; ++i)
        t[ty + i * 8][tx] = in[(size_t)(r0 + ty + i * 8) * D_ + c0 + tx];
    __syncthreads();
#pragma unroll
    for (int i = 0; i < 4; ++i) {
        const int cc = c0 + ty + i * 8;
        float v = t[tx][ty + i * 8];
        __half h = __float2half_rn(v);
        __half l = __float2half_rn(v - __half2float(h));
        out[(size_t)cc * (2 * D_) + r0 + tx]      = h;
        out[(size_t)cc * (2 * D_) + D_ + r0 + tx] = l;
    }
}

// ---------------------------------------------------------------------------
// Row softmax over TK_=2048, in place + fp16 (hi-only) emit
// ---------------------------------------------------------------------------
__global__ void softmax2048(float* __restrict__ data, __half* __restrict__ a16)
{
    __shared__ float red[8];
    const size_t row = blockIdx.x;
    float* p = data + row * (size_t)TK_;
    const int tid = threadIdx.x, lane = tid & 31, wid = tid >> 5;

    float4 v0 = ((const float4*)p)[tid];
    float4 v1 = ((const float4*)p)[tid + 256];

    float mx = fmaxf(fmaxf(fmaxf(v0.x, v0.y), fmaxf(v0.z, v0.w)),
                     fmaxf(fmaxf(v1.x, v1.y), fmaxf(v1.z, v1.w)));
#pragma unroll
    for (int o = 16; o > 0; o >>= 1) mx = fmaxf(mx, __shfl_xor_sync(~0u, mx, o));
    if (lane == 0) red[wid] = mx;
    __syncthreads();
    mx = red[0];
#pragma unroll
    for (int w = 1; w < 8; w++) mx = fmaxf(mx, red[w]);
    __syncthreads();

    v0.x = __expf(v0.x - mx); v0.y = __expf(v0.y - mx);
    v0.z = __expf(v0.z - mx); v0.w = __expf(v0.w - mx);
    v1.x = __expf(v1.x - mx); v1.y = __expf(v1.y - mx);
    v1.z = __expf(v1.z - mx); v1.w = __expf(v1.w - mx);

    float s = v0.x + v0.y + v0.z + v0.w + v1.x + v1.y + v1.z + v1.w;
#pragma unroll
    for (int o = 16; o > 0; o >>= 1) s += __shfl_xor_sync(~0u, s, o);
    if (lane == 0) red[wid] = s;
    __syncthreads();
    s = red[0] + red[1] + red[2] + red[3] + red[4] + red[5] + red[6] + red[7];

    const float inv = 1.0f / s;
    v0.x *= inv; v0.y *= inv; v0.z *= inv; v0.w *= inv;
    v1.x *= inv; v1.y *= inv; v1.z *= inv; v1.w *= inv;

    ((float4*)p)[tid]       = v0;
    ((float4*)p)[tid + 256] = v1;

    __half* ah = a16 + row * (size_t)TK_;
    auto emit = [&](int idx, float4 v) {
        ((__half2*)(ah + idx))[0] = __halves2half2(__float2half_rn(v.x), __float2half_rn(v.y));
        ((__half2*)(ah + idx))[1] = __halves2half2(__float2half_rn(v.z), __float2half_rn(v.w));
    };
    emit(tid * 4, v0);
    emit((tid + 256) * 4, v1);
}

// ---------------------------------------------------------------------------
// kernel_launch — two-stream schedule with 2 coarse batch-groups.
// Main stream (0): enc split, W split, keys, score(g0), score(g1), ctx(g0), ctx(g1)
// Side stream    : dec split, encT transpose, softmax(g0), softmax(g1)
// Overlaps: conversions ∥ keys; softmax(g0) ∥ score(g1); softmax(g1) ∥ ctx(g0).
// ---------------------------------------------------------------------------
extern "C" void kernel_launch(void* const* d_in, const int* in_sizes, int n_in,
                              void* d_out, int out_size)
{
    (void)in_sizes; (void)n_in; (void)out_size;

    const float* dec = (const float*)d_in[0];
    const float* enc = (const float*)d_in[1];
    const float* wk  = (const float*)d_in[2];
    const float* wb  = (const float*)d_in[3];

    float* ctx = (float*)d_out;                            // [B, TQ, D]
    float* ali = (float*)d_out + (size_t)B_ * TQ_ * D_;    // [B, TQ, TK]

    __half *dec16, *enc16, *encT16, *keys16, *alg16, *w16T;
    cudaGetSymbolAddress((void**)&dec16,  g_dec16);
    cudaGetSymbolAddress((void**)&enc16,  g_enc16);
    cudaGetSymbolAddress((void**)&encT16, g_encT16);
    cudaGetSymbolAddress((void**)&keys16, g_keys16);
    cudaGetSymbolAddress((void**)&alg16,  g_alg16);
    cudaGetSymbolAddress((void**)&w16T,   g_w16T);

    // Lazily-created side stream + events (host/driver objects; no device alloc).
    static bool s_init = false;
    static cudaStream_t sS;
    static cudaEvent_t evFork, evConv, evScore[NGRP], evSm[NGRP];
    if (!s_init) {
        s_init = true;
        cudaStreamCreateWithFlags(&sS, cudaStreamNonBlocking);
        cudaEventCreateWithFlags(&evFork, cudaEventDisableTiming);
        cudaEventCreateWithFlags(&evConv, cudaEventDisableTiming);
        for (int g = 0; g < NGRP; ++g) {
            cudaEventCreateWithFlags(&evScore[g], cudaEventDisableTiming);
            cudaEventCreateWithFlags(&evSm[g],    cudaEventDisableTiming);
        }
        cudaFuncSetAttribute(gemm_hmma<0,3>, cudaFuncAttributeMaxDynamicSharedMemorySize, GEMM_SMEM);
        cudaFuncSetAttribute(gemm_hmma<1,3>, cudaFuncAttributeMaxDynamicSharedMemorySize, GEMM_SMEM);
        cudaFuncSetAttribute(gemm_hmma<0,1>, cudaFuncAttributeMaxDynamicSharedMemorySize, GEMM_SMEM);
    }

    const size_t t4 = (size_t)B_ * TQ_ * D_ / 4;

    // ---- fork side stream ----
    cudaEventRecord(evFork, 0);
    cudaStreamWaitEvent(sS, evFork, 0);

    // side: dec split + encT transpose (independent of main chain)
    split_rows<<<(unsigned)((t4 + 255) / 256), 256, 0, sS>>>(dec, dec16, D_, t4);
    transpose_hi<<<dim3(TK_ / 32, D_ / 32, B_), dim3(32, 8), 0, sS>>>(
        enc, encT16, TK_, D_, (size_t)TK_ * D_, (size_t)D_ * TK_);
    cudaEventRecord(evConv, sS);

    // main: enc split + W split + keys GEMM
    split_rows<<<(unsigned)((t4 + 255) / 256), 256>>>(enc, enc16, D_, t4);
    transpose_split_w<<<dim3(D_ / 32, D_ / 32), dim3(32, 8)>>>(wk, w16T);
    gemm_hmma<1,3><<<dim3(D_ / BN, (B_ * TK_) / BM, 1), 256, GEMM_SMEM>>>(
        enc16, w16T, wb, nullptr, keys16,
        2 * D_, 2 * D_, 2 * D_, D_, D_, 0, 0, 0);

    // main needs dec16 (and later encT16) from side stream
    cudaStreamWaitEvent(0, evConv, 0);

    // ---- score halves on main; softmax on side overlapping next phase ----
    for (int g = 0; g < NGRP; ++g) {
        const size_t ob = (size_t)g * BPG;
        gemm_hmma<0,3><<<dim3(TK_ / BN, TQ_ / BM, BPG), 256, GEMM_SMEM>>>(
            dec16  + ob * TQ_ * 2 * D_,
            keys16 + ob * TK_ * 2 * D_,
            nullptr,
            ali + ob * TQ_ * TK_, nullptr,
            2 * D_, 2 * D_, TK_, D_, 0,
            (size_t)TQ_ * 2 * D_, (size_t)TK_ * 2 * D_, (size_t)TQ_ * TK_);
        cudaEventRecord(evScore[g], 0);

        cudaStreamWaitEvent(sS, evScore[g], 0);
        softmax2048<<<BPG * TQ_, 256, 0, sS>>>(
            ali + ob * TQ_ * TK_, alg16 + ob * TQ_ * TK_);
        cudaEventRecord(evSm[g], sS);
    }

    for (int g = 0; g < NGRP; ++g) {
        const size_t ob = (size_t)g * BPG;
        cudaStreamWaitEvent(0, evSm[g], 0);
        gemm_hmma<0,1><<<dim3(D_ / BN, TQ_ / BM, BPG), 256, GEMM_SMEM>>>(
            alg16  + ob * TQ_ * TK_,
            encT16 + ob * D_ * TK_,
            nullptr,
            ctx + ob * TQ_ * D_, nullptr,
            TK_, TK_, D_, TK_, 0,
            (size_t)TQ_ * TK_, (size_t)D_ * TK_, (size_t)TQ_ * D_);
    }
}

// round 10
// speedup vs baseline: 1.0889x; 1.0231x over previous
#include <cuda_runtime.h>
#include <cuda_fp16.h>
#include <cstdint>
#include <cstddef>

// Problem dims (fixed)
#define B_   16
#define TQ_  2048
#define TK_  2048
#define D_   1024

// ---------------------------------------------------------------------------
// Scratch (static __device__ arrays = sanctioned no-alloc scratch)
// fp16 hi/lo split layouts: row-major [rows, 2*K], hi in cols [0,K), lo in [K,2K).
// Alignment fp16 buffer is hi-only: [rows, TK]. encT is hi-only: [B][D, TK].
// ---------------------------------------------------------------------------
__device__ __half g_dec16 [(size_t)B_ * TQ_ * 2 * D_];   // [B*TQ, 2D]
__device__ __half g_enc16 [(size_t)B_ * TK_ * 2 * D_];   // [B*TK, 2D]
__device__ __half g_encT16[(size_t)B_ * D_  * TK_];      // [B][D, TK] hi only
__device__ __half g_keys16[(size_t)B_ * TK_ * 2 * D_];   // [B*TK, 2D]
__device__ __half g_alg16 [(size_t)B_ * TQ_ * TK_];      // [B*TQ, TK] hi only
__device__ __half g_w16T  [(size_t)D_ * 2 * D_];         // [D, 2D]

__device__ __forceinline__ uint32_t smem_u32(const void* p) {
    return (uint32_t)__cvta_generic_to_shared(p);
}

#define SW128(x) ((x) ^ (((x) >> 3) & 0x70))

// ---------------------------------------------------------------------------
// HMMA GEMM, fused hi/lo segments:
//   NSEG=3: C = hiA·hiB^T + loA·hiB^T + hiA·loB^T in ONE K-pass per chunk.
//           Stage holds 4 tiles (hiA,loA,hiB,loB) = 96KB; NS=2 stages.
//   NSEG=1: plain C = A·B^T. Stage holds 2 tiles = 48KB; NS=4 stages.
// A,B fp16 row-major K-major (row strides lda/ldb); hi at col [0,K), lo [K,2K).
// CTA tile 128x256, K-chunk 64, 8 warps (2M x 4N), warp tile 64x64,
// mma.sync.m16n8k16.
// EPI=0: fp32 C.  EPI=1: bias add + hi/lo fp16 out (hi at n, lo at loOff+n).
// ---------------------------------------------------------------------------
#define BM  128
#define BN  256
#define KC  64
static constexpr int GEMM_SMEM = 196608;     // 192KB both configs

__device__ __forceinline__ void cpa16(uint32_t dst, const void* src) {
    asm volatile("cp.async.cg.shared.global [%0], [%1], 16;" :: "r"(dst), "l"(src));
}

__device__ __forceinline__ void ldsm4(uint32_t* r, uint32_t addr) {
    asm volatile("ldmatrix.sync.aligned.m8n8.x4.shared.b16 {%0,%1,%2,%3}, [%4];"
                 : "=r"(r[0]), "=r"(r[1]), "=r"(r[2]), "=r"(r[3]) : "r"(addr));
}

__device__ __forceinline__ void mma16816(float* d, const uint32_t* a,
                                         const uint32_t b0, const uint32_t b1) {
    asm volatile("mma.sync.aligned.m16n8k16.row.col.f32.f16.f16.f32 "
                 "{%0,%1,%2,%3}, {%4,%5,%6,%7}, {%8,%9}, {%0,%1,%2,%3};"
                 : "+f"(d[0]), "+f"(d[1]), "+f"(d[2]), "+f"(d[3])
                 : "r"(a[0]), "r"(a[1]), "r"(a[2]), "r"(a[3]), "r"(b0), "r"(b1));
}

// Stage tile offsets
//  NSEG=3: hiA @0 (16KB) | loA @16K (16KB) | hiB @32K (32KB) | loB @64K (32KB)
//  NSEG=1: A @0 (16KB) | B @16K (32KB)
template<int NSEG>
__device__ __forceinline__ void load_chunk(const __half* A, const __half* Bm,
                                           int lda, int ldb, int m0, int n0,
                                           int K, int kin, uint32_t stage_base,
                                           int tid) {
    const int ka = kin * KC;
    const uint32_t saH = stage_base;
    const uint32_t saL = stage_base + 16384;
    const uint32_t sbH = stage_base + (NSEG == 3 ? 32768 : 16384);
    const uint32_t sbL = stage_base + 65536;
#pragma unroll
    for (int it = 0; it < (BM * 8) / 256; ++it) {        // A: 128 rows x 8 segs
        int idx = tid + it * 256;
        int row = idx >> 3, c16 = idx & 7;
        const __half* g = A + (size_t)(m0 + row) * lda + ka + c16 * 8;
        uint32_t sw = SW128(row * 128 + c16 * 16);
        cpa16(saH + sw, g);
        if (NSEG == 3) cpa16(saL + sw, g + K);
    }
#pragma unroll
    for (int it = 0; it < (BN * 8) / 256; ++it) {        // B: 256 rows x 8 segs
        int idx = tid + it * 256;
        int row = idx >> 3, c16 = idx & 7;
        const __half* g = Bm + (size_t)(n0 + row) * ldb + ka + c16 * 8;
        uint32_t sw = SW128(row * 128 + c16 * 16);
        cpa16(sbH + sw, g);
        if (NSEG == 3) cpa16(sbL + sw, g + K);
    }
}

template<int EPI, int NSEG>
__global__ __launch_bounds__(256, 1)
void gemm_hmma(const __half* __restrict__ A, const __half* __restrict__ Bm,
               const float* __restrict__ bias,
               float* __restrict__ Cf, __half* __restrict__ Ch,
               int lda, int ldb, int ldc, int K, int loOff,
               size_t sA, size_t sB, size_t sC)
{
    constexpr int NSs = (NSEG == 3) ? 2 : 4;
    constexpr int STG = (NSEG == 3) ? 98304 : 49152;

    extern __shared__ __align__(1024) char smem[];
    const uint32_t smem_base = smem_u32(smem);
    const int tid = threadIdx.x, wid = tid >> 5, lid = tid & 31;
    const int bz = blockIdx.z;
    A  += (size_t)bz * sA;
    Bm += (size_t)bz * sB;

    const int m0 = blockIdx.y * BM;
    const int n0 = blockIdx.x * BN;

    const int nk = K / KC;

    // warp layout: 2 (M) x 4 (N); warp tile 64x64
    const int warp_m = wid & 1;
    const int warp_n = wid >> 1;

    float acc[4][8][4];
#pragma unroll
    for (int t = 0; t < 4; ++t)
#pragma unroll
        for (int j = 0; j < 8; ++j)
#pragma unroll
            for (int c = 0; c < 4; ++c) acc[t][j][c] = 0.f;

    // ldmatrix per-lane address components
    const int aRow = warp_m * 64 + (lid & 15);
    const int aK   = (lid & 16) >> 1;       // 0 or 8
    const int bRow = warp_n * 64 + (lid & 7) + ((lid & 16) >> 1);
    const int bK   = (lid & 8);             // 0 or 8

    // ---- prologue: fill NSs-1 stages ----
#pragma unroll
    for (int i = 0; i < NSs - 1; ++i) {
        load_chunk<NSEG>(A, Bm, lda, ldb, m0, n0, K, i,
                         smem_base + i * STG, tid);
        asm volatile("cp.async.commit_group;" ::: "memory");
    }

    for (int cc = 0; cc < nk; ++cc) {
        asm volatile("cp.async.wait_group %0;" :: "n"(NSs - 2));
        __syncthreads();

        // prefetch chunk cc+NSs-1 into the stage freed at iter cc-1
        {
            const int cl = cc + NSs - 1;
            if (cl < nk)
                load_chunk<NSEG>(A, Bm, lda, ldb, m0, n0, K, cl,
                                 smem_base + (cl & (NSs - 1)) * STG, tid);
            asm volatile("cp.async.commit_group;" ::: "memory");
        }

        // ---- compute on stage cc%NSs ----
        const uint32_t st  = smem_base + (cc & (NSs - 1)) * STG;
        const uint32_t saH = st;
        const uint32_t saL = st + 16384;
        const uint32_t sbH = st + (NSEG == 3 ? 32768 : 16384);
        const uint32_t sbL = st + 65536;
#pragma unroll
        for (int kk = 0; kk < KC; kk += 16) {
            uint32_t aH[4][4], bH[4][4];
#pragma unroll
            for (int t = 0; t < 4; ++t)
                ldsm4(aH[t], saH + SW128((aRow + t * 16) * 128 + (kk + aK) * 2));
#pragma unroll
            for (int g = 0; g < 4; ++g)
                ldsm4(bH[g], sbH + SW128((bRow + g * 16) * 128 + (kk + bK) * 2));
            // P0: hiA x hiB
#pragma unroll
            for (int t = 0; t < 4; ++t)
#pragma unroll
                for (int j = 0; j < 8; ++j)
                    mma16816(acc[t][j], aH[t],
                             bH[j >> 1][(j & 1) * 2], bH[j >> 1][(j & 1) * 2 + 1]);
            if (NSEG == 3) {
                // P1: loA x hiB
                uint32_t aL[4][4];
#pragma unroll
                for (int t = 0; t < 4; ++t)
                    ldsm4(aL[t], saL + SW128((aRow + t * 16) * 128 + (kk + aK) * 2));
#pragma unroll
                for (int t = 0; t < 4; ++t)
#pragma unroll
                    for (int j = 0; j < 8; ++j)
                        mma16816(acc[t][j], aL[t],
                                 bH[j >> 1][(j & 1) * 2], bH[j >> 1][(j & 1) * 2 + 1]);
                // P2: hiA x loB
                uint32_t bL[4][4];
#pragma unroll
                for (int g = 0; g < 4; ++g)
                    ldsm4(bL[g], sbL + SW128((bRow + g * 16) * 128 + (kk + bK) * 2));
#pragma unroll
                for (int t = 0; t < 4; ++t)
#pragma unroll
                    for (int j = 0; j < 8; ++j)
                        mma16816(acc[t][j], aH[t],
                                 bL[j >> 1][(j & 1) * 2], bL[j >> 1][(j & 1) * 2 + 1]);
            }
        }
    }

    // ---- epilogue ----
    const int g8 = lid >> 2;
    const int tg = lid & 3;
#pragma unroll
    for (int t = 0; t < 4; ++t) {
        const int rbase = m0 + warp_m * 64 + t * 16 + g8;
#pragma unroll
        for (int j = 0; j < 8; ++j) {
            const int col = n0 + warp_n * 64 + j * 8 + tg * 2;
            if (EPI == 0) {
                float* p0 = Cf + (size_t)bz * sC + (size_t)rbase * ldc + col;
                float* p1 = p0 + (size_t)8 * ldc;
                ((float2*)p0)[0] = make_float2(acc[t][j][0], acc[t][j][1]);
                ((float2*)p1)[0] = make_float2(acc[t][j][2], acc[t][j][3]);
            } else {
                const float b0 = bias[col], b1 = bias[col + 1];
#pragma unroll
                for (int hrow = 0; hrow < 2; ++hrow) {
                    const int row = rbase + hrow * 8;
                    float v0 = acc[t][j][hrow * 2 + 0] + b0;
                    float v1 = acc[t][j][hrow * 2 + 1] + b1;
                    __half h0 = __float2half_rn(v0), h1 = __float2half_rn(v1);
                    __half l0 = __float2half_rn(v0 - __half2float(h0));
                    __half l1 = __float2half_rn(v1 - __half2float(h1));
                    *(__half2*)(Ch + (size_t)row * ldc + col)         = __halves2half2(h0, h1);
                    *(__half2*)(Ch + (size_t)row * ldc + loOff + col) = __halves2half2(l0, l1);
                }
            }
        }
    }
}

// ---------------------------------------------------------------------------
// fp32 [rows, C] -> fp16 [rows, 2C] hi|lo split (used for dec)
// ---------------------------------------------------------------------------
__global__ void split_rows(const float* __restrict__ in, __half* __restrict__ out,
                           int C, size_t total4)
{
    size_t i = (size_t)blockIdx.x * blockDim.x + threadIdx.x;
    if (i >= total4) return;
    const int c4 = C / 4;
    size_t r = i / c4;
    int c = (int)(i % c4) * 4;
    float4 v = ((const float4*)in)[i];
    __half h0 = __float2half_rn(v.x), h1 = __float2half_rn(v.y);
    __half h2 = __float2half_rn(v.z), h3 = __float2half_rn(v.w);
    __half l0 = __float2half_rn(v.x - __half2float(h0));
    __half l1 = __float2half_rn(v.y - __half2float(h1));
    __half l2 = __float2half_rn(v.z - __half2float(h2));
    __half l3 = __float2half_rn(v.w - __half2float(h3));
    __half* ph = out + r * (size_t)(2 * C) + c;
    ((__half2*)ph)[0] = __halves2half2(h0, h1);
    ((__half2*)ph)[1] = __halves2half2(h2, h3);
    __half* pl = ph + C;
    ((__half2*)pl)[0] = __halves2half2(l0, l1);
    ((__half2*)pl)[1] = __halves2half2(l2, l3);
}

// ---------------------------------------------------------------------------
// Fused enc conversion: one read of enc [B][TK, D] fp32 produces
//   enc16  [B*TK, 2D] hi|lo  (keys GEMM A operand)
//   encT16 [B][D, TK]  hi    (context GEMM B operand)
// Tile 32x32 per block, block (32,8), grid (TK/32, D/32, B).
// ---------------------------------------------------------------------------
__global__ void enc_convert(const float* __restrict__ enc,
                            __half* __restrict__ enc16,
                            __half* __restrict__ encT16)
{
    __shared__ float t[32][33];
    const int bz = blockIdx.z;
    const float* in = enc + (size_t)bz * TK_ * D_;
    const int r0 = blockIdx.x * 32;          // TK dim
    const int c0 = blockIdx.y * 32;          // D dim
    const int tx = threadIdx.x, ty = threadIdx.y;  // 32 x 8

#pragma unroll
    for (int i = 0; i < 4; ++i)
        t[ty + i * 8][tx] = in[(size_t)(r0 + ty + i * 8) * D_ + c0 + tx];
    __syncthreads();

    // enc16: rows along TK, cols along D (coalesced in tx = D dim)
#pragma unroll
    for (int i = 0; i < 4; ++i) {
        const int rr = r0 + ty + i * 8;
        float v = t[ty + i * 8][tx];
        __half h = __float2half_rn(v);
        __half l = __float2half_rn(v - __half2float(h));
        __half* p = enc16 + ((size_t)bz * TK_ + rr) * (2 * D_) + c0 + tx;
        p[0]  = h;
        p[D_] = l;
    }
    // encT16: rows along D, cols along TK (coalesced in tx = TK dim)
#pragma unroll
    for (int i = 0; i < 4; ++i) {
        const int cc = c0 + ty + i * 8;
        float v = t[tx][ty + i * 8];         // enc[r0+tx][cc]
        encT16[(size_t)bz * D_ * TK_ + (size_t)cc * TK_ + r0 + tx] = __float2half_rn(v);
    }
}

// ---------------------------------------------------------------------------
// W transpose + hi/lo split: in [D, D] fp32 -> out [D, 2D] fp16,
// out[e][d] = hi(W[d][e]), out[e][D+d] = lo(W[d][e]).
// ---------------------------------------------------------------------------
__global__ void transpose_split_w(const float* __restrict__ in, __half* __restrict__ out)
{
    __shared__ float t[32][33];
    const int r0 = blockIdx.x * 32, c0 = blockIdx.y * 32;
    const int tx = threadIdx.x, ty = threadIdx.y;  // 32 x 8
#pragma unroll
    for (int i = 0; i < 4; ++i)
        t[ty + i * 8][tx] = in[(size_t)(r0 + ty + i * 8) * D_ + c0 + tx];
    __syncthreads();
#pragma unroll
    for (int i = 0; i < 4; ++i) {
        const int cc = c0 + ty + i * 8;
        float v = t[tx][ty + i * 8];
        __half h = __float2half_rn(v);
        __half l = __float2half_rn(v - __half2float(h));
        out[(size_t)cc * (2 * D_) + r0 + tx]      = h;
        out[(size_t)cc * (2 * D_) + D_ + r0 + tx] = l;
    }
}

// ---------------------------------------------------------------------------
// Row softmax over TK_=2048, in place + fp16 (hi-only) emit
// ---------------------------------------------------------------------------
__global__ void softmax2048(float* __restrict__ data, __half* __restrict__ a16)
{
    __shared__ float red[8];
    const size_t row = blockIdx.x;
    float* p = data + row * (size_t)TK_;
    const int tid = threadIdx.x, lane = tid & 31, wid = tid >> 5;

    float4 v0 = ((const float4*)p)[tid];
    float4 v1 = ((const float4*)p)[tid + 256];

    float mx = fmaxf(fmaxf(fmaxf(v0.x, v0.y), fmaxf(v0.z, v0.w)),
                     fmaxf(fmaxf(v1.x, v1.y), fmaxf(v1.z, v1.w)));
#pragma unroll
    for (int o = 16; o > 0; o >>= 1) mx = fmaxf(mx, __shfl_xor_sync(~0u, mx, o));
    if (lane == 0) red[wid] = mx;
    __syncthreads();
    mx = red[0];
#pragma unroll
    for (int w = 1; w < 8; w++) mx = fmaxf(mx, red[w]);
    __syncthreads();

    v0.x = __expf(v0.x - mx); v0.y = __expf(v0.y - mx);
    v0.z = __expf(v0.z - mx); v0.w = __expf(v0.w - mx);
    v1.x = __expf(v1.x - mx); v1.y = __expf(v1.y - mx);
    v1.z = __expf(v1.z - mx); v1.w = __expf(v1.w - mx);

    float s = v0.x + v0.y + v0.z + v0.w + v1.x + v1.y + v1.z + v1.w;
#pragma unroll
    for (int o = 16; o > 0; o >>= 1) s += __shfl_xor_sync(~0u, s, o);
    if (lane == 0) red[wid] = s;
    __syncthreads();
    s = red[0] + red[1] + red[2] + red[3] + red[4] + red[5] + red[6] + red[7];

    const float inv = 1.0f / s;
    v0.x *= inv; v0.y *= inv; v0.z *= inv; v0.w *= inv;
    v1.x *= inv; v1.y *= inv; v1.z *= inv; v1.w *= inv;

    ((float4*)p)[tid]       = v0;
    ((float4*)p)[tid + 256] = v1;

    __half* ah = a16 + row * (size_t)TK_;
    auto emit = [&](int idx, float4 v) {
        ((__half2*)(ah + idx))[0] = __halves2half2(__float2half_rn(v.x), __float2half_rn(v.y));
        ((__half2*)(ah + idx))[1] = __halves2half2(__float2half_rn(v.z), __float2half_rn(v.w));
    };
    emit(tid * 4, v0);
    emit((tid + 256) * 4, v1);
}

// ---------------------------------------------------------------------------
// kernel_launch — single stream (overlap attempts R8/R9 were neutral/negative).
// dec split -> enc fused convert -> W split -> keys -> score -> softmax -> ctx
// ---------------------------------------------------------------------------
extern "C" void kernel_launch(void* const* d_in, const int* in_sizes, int n_in,
                              void* d_out, int out_size)
{
    (void)in_sizes; (void)n_in; (void)out_size;

    const float* dec = (const float*)d_in[0];
    const float* enc = (const float*)d_in[1];
    const float* wk  = (const float*)d_in[2];
    const float* wb  = (const float*)d_in[3];

    float* ctx = (float*)d_out;                            // [B, TQ, D]
    float* ali = (float*)d_out + (size_t)B_ * TQ_ * D_;    // [B, TQ, TK]

    __half *dec16, *enc16, *encT16, *keys16, *alg16, *w16T;
    cudaGetSymbolAddress((void**)&dec16,  g_dec16);
    cudaGetSymbolAddress((void**)&enc16,  g_enc16);
    cudaGetSymbolAddress((void**)&encT16, g_encT16);
    cudaGetSymbolAddress((void**)&keys16, g_keys16);
    cudaGetSymbolAddress((void**)&alg16,  g_alg16);
    cudaGetSymbolAddress((void**)&w16T,   g_w16T);

    cudaFuncSetAttribute(gemm_hmma<0,3>, cudaFuncAttributeMaxDynamicSharedMemorySize, GEMM_SMEM);
    cudaFuncSetAttribute(gemm_hmma<1,3>, cudaFuncAttributeMaxDynamicSharedMemorySize, GEMM_SMEM);
    cudaFuncSetAttribute(gemm_hmma<0,1>, cudaFuncAttributeMaxDynamicSharedMemorySize, GEMM_SMEM);

    // --- conversions ---
    {
        size_t t4 = (size_t)B_ * TQ_ * D_ / 4;
        split_rows<<<(unsigned)((t4 + 255) / 256), 256>>>(dec, dec16, D_, t4);
    }
    enc_convert<<<dim3(TK_ / 32, D_ / 32, B_), dim3(32, 8)>>>(enc, enc16, encT16);
    transpose_split_w<<<dim3(D_ / 32, D_ / 32), dim3(32, 8)>>>(wk, w16T);

    // --- keys = enc·W + bias -> keys16 hi/lo (fused 3-seg) ---
    gemm_hmma<1,3><<<dim3(D_ / BN, (B_ * TK_) / BM, 1), 256, GEMM_SMEM>>>(
        enc16, w16T, wb, nullptr, keys16,
        2 * D_, 2 * D_, 2 * D_, D_, D_, 0, 0, 0);

    // --- score = dec·keys^T -> ali fp32 (batched, fused 3-seg) ---
    gemm_hmma<0,3><<<dim3(TK_ / BN, TQ_ / BM, B_), 256, GEMM_SMEM>>>(
        dec16, keys16, nullptr, ali, nullptr,
        2 * D_, 2 * D_, TK_, D_, 0,
        (size_t)TQ_ * 2 * D_, (size_t)TK_ * 2 * D_, (size_t)TQ_ * TK_);

    // --- softmax + fp16 hi emit ---
    softmax2048<<<B_ * TQ_, 256>>>(ali, alg16);

    // --- context = align·enc^T(hi) -> ctx fp32 (batched, single-pass) ---
    gemm_hmma<0,1><<<dim3(D_ / BN, TQ_ / BM, B_), 256, GEMM_SMEM>>>(
        alg16, encT16, nullptr, ctx, nullptr,
        TK_, TK_, D_, TK_, 0,
        (size_t)TQ_ * TK_, (size_t)D_ * TK_, (size_t)TQ_ * D_);
}